// round 2
// baseline (speedup 1.0000x reference)
#include <cuda_runtime.h>
#include <cuda_bf16.h>
#include <cstdint>

// Problem constants (fixed by the dataset)
#define NN 50000
#define DD 128
#define EE 800000

// Scratch (no allocations allowed -> __device__ globals)
__device__ float g_deg[NN];
__device__ float g_dinv[NN];
__device__ float g_h[(size_t)NN * DD];   // GEMM output (messages to gather)
__device__ float g_a[(size_t)NN * DD];   // layer-1 aggregate

// ---------------------------------------------------------------------------
// Degree / normalization
// ---------------------------------------------------------------------------
__global__ void k_deg_init(int n) {
    int i = blockIdx.x * blockDim.x + threadIdx.x;
    if (i < n) g_deg[i] = 1.0f;  // self-loop
}

__global__ void k_deg_count(const int* __restrict__ dst, int e) {
    int i = blockIdx.x * blockDim.x + threadIdx.x;
    if (i < e) atomicAdd(&g_deg[dst[i]], 1.0f);
}

__global__ void k_dinv(int n) {
    int i = blockIdx.x * blockDim.x + threadIdx.x;
    if (i < n) g_dinv[i] = rsqrtf(g_deg[i]);
}

// ---------------------------------------------------------------------------
// GEMM: Y[n,128] = (relu?)X[n,128] @ W[128,128]
// block = 128 threads, 32 rows per block. Thread t owns output column t.
// ---------------------------------------------------------------------------
template <bool RELU>
__global__ __launch_bounds__(128) void k_gemm(const float* __restrict__ X,
                                              const float* __restrict__ W,
                                              float* __restrict__ Y, int n) {
    __shared__ float xs[32 * 128];
    const int tid  = threadIdx.x;        // 0..127 = output column
    const int row0 = blockIdx.x * 32;

#pragma unroll
    for (int r = 0; r < 32; r++) {
        int row = row0 + r;
        float v = 0.0f;
        if (row < n) v = X[(size_t)row * DD + tid];
        if (RELU) v = fmaxf(v, 0.0f);
        xs[r * 128 + tid] = v;
    }
    __syncthreads();

    float acc[32];
#pragma unroll
    for (int r = 0; r < 32; r++) acc[r] = 0.0f;

#pragma unroll 4
    for (int k0 = 0; k0 < 128; k0 += 4) {
        float w0 = __ldg(&W[(k0 + 0) * 128 + tid]);
        float w1 = __ldg(&W[(k0 + 1) * 128 + tid]);
        float w2 = __ldg(&W[(k0 + 2) * 128 + tid]);
        float w3 = __ldg(&W[(k0 + 3) * 128 + tid]);
#pragma unroll
        for (int r = 0; r < 32; r++) {
            float4 xv = *reinterpret_cast<const float4*>(&xs[r * 128 + k0]);
            acc[r] = fmaf(xv.w, w3, fmaf(xv.z, w2, fmaf(xv.y, w1, fmaf(xv.x, w0, acc[r]))));
        }
    }

#pragma unroll
    for (int r = 0; r < 32; r++) {
        int row = row0 + r;
        if (row < n) Y[(size_t)row * DD + tid] = acc[r];
    }
}

// ---------------------------------------------------------------------------
// Seed: out[i,c] = h[i,c] * dinv[i]^2 (self-loop message) + b[c]
// Fully initializes 'out' (d_out is poisoned by the harness).
// ---------------------------------------------------------------------------
__global__ void k_seed(const float* __restrict__ h, const float* __restrict__ b,
                       float* __restrict__ out, int n) {
    int t = blockIdx.x * blockDim.x + threadIdx.x;
    if (t >= n * DD) return;
    int i = t >> 7;
    int c = t & 127;
    float di = g_dinv[i];
    out[t] = fmaf(h[t], di * di, b[c]);
}

// ---------------------------------------------------------------------------
// Edge scatter: one warp per edge. Lane l handles float4 chunk l of the row.
// out[dst] += h[src] * (dinv[src]*dinv[dst]) via red.global.add.v4.f32
// ---------------------------------------------------------------------------
__global__ __launch_bounds__(256) void k_scatter(const int* __restrict__ src,
                                                 const int* __restrict__ dst,
                                                 const float* __restrict__ h,
                                                 float* __restrict__ out, int e) {
    int g    = blockIdx.x * blockDim.x + threadIdx.x;
    int edge = g >> 5;
    int lane = g & 31;
    if (edge >= e) return;

    int s = __ldg(&src[edge]);
    int d = __ldg(&dst[edge]);
    float nrm = g_dinv[s] * g_dinv[d];

    float4 v = __ldg(reinterpret_cast<const float4*>(h + (size_t)s * DD) + lane);
    float* p = out + (size_t)d * DD + lane * 4;
    asm volatile("red.global.add.v4.f32 [%0], {%1, %2, %3, %4};"
                 :: "l"(p), "f"(v.x * nrm), "f"(v.y * nrm),
                    "f"(v.z * nrm), "f"(v.w * nrm)
                 : "memory");
}

// ---------------------------------------------------------------------------
// Launch
// ---------------------------------------------------------------------------
extern "C" void kernel_launch(void* const* d_in, const int* in_sizes, int n_in,
                              void* d_out, int out_size) {
    const float* x  = (const float*)d_in[0];
    const int*   ei = (const int*)d_in[1];
    const float* W1 = (const float*)d_in[2];
    const float* b1 = (const float*)d_in[3];
    const float* W2 = (const float*)d_in[4];
    const float* b2 = (const float*)d_in[5];
    float* out = (float*)d_out;

    const int n = in_sizes[0] / DD;   // 50000
    const int e = in_sizes[1] / 2;    // 800000
    const int* src = ei;
    const int* dst = ei + e;

    float *p_h = nullptr, *p_a = nullptr;
    cudaGetSymbolAddress((void**)&p_h, g_h);
    cudaGetSymbolAddress((void**)&p_a, g_a);

    const int T = 256;

    // normalization
    k_deg_init<<<(n + T - 1) / T, T>>>(n);
    k_deg_count<<<(e + T - 1) / T, T>>>(dst, e);
    k_dinv<<<(n + T - 1) / T, T>>>(n);

    const int gemm_blocks = (n + 31) / 32;
    const long long nd = (long long)n * DD;
    const int seed_blocks = (int)((nd + T - 1) / T);
    const long long ethreads = (long long)e * 32;
    const int scat_blocks = (int)((ethreads + T - 1) / T);

    // Layer 1
    k_gemm<false><<<gemm_blocks, 128>>>(x, W1, p_h, n);
    k_seed<<<seed_blocks, T>>>(p_h, b1, p_a, n);
    k_scatter<<<scat_blocks, T>>>(src, dst, p_h, p_a, e);

    // Layer 2 (ReLU fused into GEMM input read)
    k_gemm<true><<<gemm_blocks, 128>>>(p_a, W2, p_h, n);
    k_seed<<<seed_blocks, T>>>(p_h, b2, out, n);
    k_scatter<<<scat_blocks, T>>>(src, dst, p_h, out, e);
}

// round 3
// speedup vs baseline: 1.2702x; 1.2702x over previous
#include <cuda_runtime.h>
#include <cuda_bf16.h>
#include <cstdint>

#define NN 50000
#define DD 128
#define EE 800000

// Scratch (__device__ globals; no allocations allowed)
__device__ int   g_cnt[NN];        // in-degree counts (excl self)
__device__ int   g_rowptr[NN + 1]; // CSR row pointers (in-edges by dst)
__device__ int   g_cursor[NN];     // fill cursors
__device__ int   g_col[EE];        // CSR column (src node ids)
__device__ float g_dinv[NN];
__device__ float g_hs[(size_t)NN * DD];  // hs = (X@W) * dinv[row]
__device__ float g_a[(size_t)NN * DD];   // layer-1 output (pre-relu)

// ---------------------------------------------------------------------------
// CSR build
// ---------------------------------------------------------------------------
__global__ void k_zero(int n) {
    int i = blockIdx.x * blockDim.x + threadIdx.x;
    if (i < n) g_cnt[i] = 0;
}

__global__ void k_hist(const int* __restrict__ dst, int e) {
    int i = blockIdx.x * blockDim.x + threadIdx.x;
    if (i < e) atomicAdd(&g_cnt[dst[i]], 1);
}

// Single-block exclusive scan over g_cnt -> g_rowptr/g_cursor, plus dinv.
__global__ __launch_bounds__(1024) void k_scan(int n) {
    __shared__ int ssum[1024];
    const int per = (n + 1023) / 1024;
    int t = threadIdx.x;
    int beg = t * per;
    int end = min(beg + per, n);

    int local = 0;
    for (int i = beg; i < end; i++) local += g_cnt[i];
    ssum[t] = local;
    __syncthreads();

    // Hillis–Steele inclusive scan
    for (int off = 1; off < 1024; off <<= 1) {
        int v = (t >= off) ? ssum[t - off] : 0;
        __syncthreads();
        ssum[t] += v;
        __syncthreads();
    }

    int prefix = (t == 0) ? 0 : ssum[t - 1];
    for (int i = beg; i < end; i++) {
        int c = g_cnt[i];
        g_rowptr[i] = prefix;
        g_cursor[i] = prefix;
        g_dinv[i]   = rsqrtf((float)(c + 1));  // +1 self-loop
        prefix += c;
    }
    if (t == 1023) g_rowptr[n] = prefix;  // == E
}

__global__ void k_fill(const int* __restrict__ src, const int* __restrict__ dst, int e) {
    int i = blockIdx.x * blockDim.x + threadIdx.x;
    if (i < e) {
        int pos = atomicAdd(&g_cursor[dst[i]], 1);
        g_col[pos] = src[i];
    }
}

// ---------------------------------------------------------------------------
// GEMM: hs[row] = ((relu?)X[row] @ W) * dinv[row]
// 256 threads, 64 rows x 128 cols per block, 8x4 micro-tile per thread.
// ---------------------------------------------------------------------------
template <bool RELU>
__global__ __launch_bounds__(256) void k_gemm(const float* __restrict__ X,
                                              const float* __restrict__ W,
                                              float* __restrict__ Y, int n) {
    __shared__ float xs[64][128];
    const int tid  = threadIdx.x;
    const int row0 = blockIdx.x * 64;

    // Cooperative X-tile load (float4 granularity): 64*32 float4s / 256 threads
#pragma unroll
    for (int i = tid; i < 64 * 32; i += 256) {
        int r  = i >> 5;
        int c4 = i & 31;
        int row = row0 + r;
        float4 v = make_float4(0.f, 0.f, 0.f, 0.f);
        if (row < n) v = __ldg(reinterpret_cast<const float4*>(X + (size_t)row * DD) + c4);
        if (RELU) {
            v.x = fmaxf(v.x, 0.f); v.y = fmaxf(v.y, 0.f);
            v.z = fmaxf(v.z, 0.f); v.w = fmaxf(v.w, 0.f);
        }
        *reinterpret_cast<float4*>(&xs[r][c4 * 4]) = v;
    }
    __syncthreads();

    const int tx = tid & 31;   // column group: cols tx*4 .. tx*4+3
    const int ty = tid >> 5;   // row group:    rows ty*8 .. ty*8+7

    float acc[8][4];
#pragma unroll
    for (int r = 0; r < 8; r++)
#pragma unroll
        for (int c = 0; c < 4; c++) acc[r][c] = 0.f;

#pragma unroll 8
    for (int k = 0; k < 128; k += 4) {
        float4 w0 = __ldg(reinterpret_cast<const float4*>(W + (k + 0) * 128) + tx);
        float4 w1 = __ldg(reinterpret_cast<const float4*>(W + (k + 1) * 128) + tx);
        float4 w2 = __ldg(reinterpret_cast<const float4*>(W + (k + 2) * 128) + tx);
        float4 w3 = __ldg(reinterpret_cast<const float4*>(W + (k + 3) * 128) + tx);
#pragma unroll
        for (int r = 0; r < 8; r++) {
            float4 xv = *reinterpret_cast<const float4*>(&xs[ty * 8 + r][k]);  // broadcast
            acc[r][0] = fmaf(xv.x, w0.x, fmaf(xv.y, w1.x, fmaf(xv.z, w2.x, fmaf(xv.w, w3.x, acc[r][0]))));
            acc[r][1] = fmaf(xv.x, w0.y, fmaf(xv.y, w1.y, fmaf(xv.z, w2.y, fmaf(xv.w, w3.y, acc[r][1]))));
            acc[r][2] = fmaf(xv.x, w0.z, fmaf(xv.y, w1.z, fmaf(xv.z, w2.z, fmaf(xv.w, w3.z, acc[r][2]))));
            acc[r][3] = fmaf(xv.x, w0.w, fmaf(xv.y, w1.w, fmaf(xv.z, w2.w, fmaf(xv.w, w3.w, acc[r][3]))));
        }
    }

#pragma unroll
    for (int r = 0; r < 8; r++) {
        int row = row0 + ty * 8 + r;
        if (row < n) {
            float di = g_dinv[row];
            float4 o = make_float4(acc[r][0] * di, acc[r][1] * di,
                                   acc[r][2] * di, acc[r][3] * di);
            *(reinterpret_cast<float4*>(Y + (size_t)row * DD) + tx) = o;
        }
    }
}

// ---------------------------------------------------------------------------
// Gather-aggregate: out[i] = dinv[i] * (hs[i] + sum_{in-edges} hs[src]) + b
// One warp per node; lane owns one float4 chunk of the 128-wide row.
// ---------------------------------------------------------------------------
__global__ __launch_bounds__(256) void k_gather(const float* __restrict__ hs,
                                                const float* __restrict__ b,
                                                float* __restrict__ out, int n) {
    int g    = blockIdx.x * blockDim.x + threadIdx.x;
    int node = g >> 5;
    int lane = g & 31;
    if (node >= n) return;

    const float4* H = reinterpret_cast<const float4*>(hs);
    int beg = g_rowptr[node];
    int end = g_rowptr[node + 1];

    float4 acc = __ldg(&H[node * 32 + lane]);  // self term

    int e = beg;
    for (; e + 4 <= end; e += 4) {
        int s0 = g_col[e + 0], s1 = g_col[e + 1];
        int s2 = g_col[e + 2], s3 = g_col[e + 3];
        float4 v0 = __ldg(&H[s0 * 32 + lane]);
        float4 v1 = __ldg(&H[s1 * 32 + lane]);
        float4 v2 = __ldg(&H[s2 * 32 + lane]);
        float4 v3 = __ldg(&H[s3 * 32 + lane]);
        acc.x += (v0.x + v1.x) + (v2.x + v3.x);
        acc.y += (v0.y + v1.y) + (v2.y + v3.y);
        acc.z += (v0.z + v1.z) + (v2.z + v3.z);
        acc.w += (v0.w + v1.w) + (v2.w + v3.w);
    }
    for (; e < end; e++) {
        float4 v = __ldg(&H[g_col[e] * 32 + lane]);
        acc.x += v.x; acc.y += v.y; acc.z += v.z; acc.w += v.w;
    }

    float di  = g_dinv[node];
    float4 bb = __ldg(reinterpret_cast<const float4*>(b) + lane);
    float4 o;
    o.x = fmaf(acc.x, di, bb.x);
    o.y = fmaf(acc.y, di, bb.y);
    o.z = fmaf(acc.z, di, bb.z);
    o.w = fmaf(acc.w, di, bb.w);
    reinterpret_cast<float4*>(out)[node * 32 + lane] = o;
}

// ---------------------------------------------------------------------------
// Launch
// ---------------------------------------------------------------------------
extern "C" void kernel_launch(void* const* d_in, const int* in_sizes, int n_in,
                              void* d_out, int out_size) {
    const float* x  = (const float*)d_in[0];
    const int*   ei = (const int*)d_in[1];
    const float* W1 = (const float*)d_in[2];
    const float* b1 = (const float*)d_in[3];
    const float* W2 = (const float*)d_in[4];
    const float* b2 = (const float*)d_in[5];
    float* out = (float*)d_out;

    const int n = in_sizes[0] / DD;   // 50000
    const int e = in_sizes[1] / 2;    // 800000
    const int* src = ei;
    const int* dst = ei + e;

    float *p_hs = nullptr, *p_a = nullptr;
    cudaGetSymbolAddress((void**)&p_hs, g_hs);
    cudaGetSymbolAddress((void**)&p_a,  g_a);

    const int T = 256;

    // CSR + normalization
    k_zero<<<(n + T - 1) / T, T>>>(n);
    k_hist<<<(e + T - 1) / T, T>>>(dst, e);
    k_scan<<<1, 1024>>>(n);
    k_fill<<<(e + T - 1) / T, T>>>(src, dst, e);

    const int gemm_blocks = (n + 63) / 64;
    const long long nwt = (long long)n * 32;
    const int gath_blocks = (int)((nwt + T - 1) / T);

    // Layer 1
    k_gemm<false><<<gemm_blocks, 256>>>(x, W1, p_hs, n);
    k_gather<<<gath_blocks, T>>>(p_hs, b1, p_a, n);

    // Layer 2 (ReLU fused into GEMM tile load)
    k_gemm<true><<<gemm_blocks, 256>>>(p_a, W2, p_hs, n);
    k_gather<<<gath_blocks, T>>>(p_hs, b2, out, n);
}

// round 5
// speedup vs baseline: 2.0006x; 1.5749x over previous
#include <cuda_runtime.h>
#include <cuda_bf16.h>
#include <cstdint>

#define NN 50000
#define DD 128
#define EE 800000
#define SCAN_BS 1024
#define NB_MAX 64

// ---------------------------------------------------------------------------
// Scratch (__device__ globals; no allocations allowed)
// ---------------------------------------------------------------------------
__device__ int   g_cnt[NN];
__device__ int   g_rowptr[NN + 1];
__device__ int   g_cursor[NN];
__device__ int   g_col[EE];
__device__ float g_dinv[NN];
__device__ int   g_bsum[NB_MAX];
__device__ float g_h[(size_t)NN * DD];   // raw GEMM output h = X@W
__device__ float g_a[(size_t)NN * DD];   // layer-1 output

// ---------------------------------------------------------------------------
// Helpers
// ---------------------------------------------------------------------------
__device__ __forceinline__ uint32_t f2tf(float f) {
    uint32_t r; asm("cvt.rna.tf32.f32 %0, %1;" : "=r"(r) : "f"(f)); return r;
}

// ---------------------------------------------------------------------------
// CSR build
// ---------------------------------------------------------------------------
__global__ void k_zero(int n) {
    int i = blockIdx.x * blockDim.x + threadIdx.x;
    if (i < n) g_cnt[i] = 0;
}

__global__ void k_hist(const int* __restrict__ dst, int e) {
    int i = blockIdx.x * blockDim.x + threadIdx.x;
    int n4 = e >> 2;
    if (i < n4) {
        int4 d = __ldg(reinterpret_cast<const int4*>(dst) + i);
        atomicAdd(&g_cnt[d.x], 1);
        atomicAdd(&g_cnt[d.y], 1);
        atomicAdd(&g_cnt[d.z], 1);
        atomicAdd(&g_cnt[d.w], 1);
    } else {
        int j = n4 * 4 + (i - n4);
        if (j < e) atomicAdd(&g_cnt[dst[j]], 1);
    }
}

__global__ __launch_bounds__(SCAN_BS) void k_scanA(int n) {
    __shared__ int s[SCAN_BS];
    int i = blockIdx.x * SCAN_BS + threadIdx.x;
    s[threadIdx.x] = (i < n) ? g_cnt[i] : 0;
    __syncthreads();
    for (int off = SCAN_BS / 2; off > 0; off >>= 1) {
        if (threadIdx.x < off) s[threadIdx.x] += s[threadIdx.x + off];
        __syncthreads();
    }
    if (threadIdx.x == 0) g_bsum[blockIdx.x] = s[0];
}

__global__ void k_scanB(int nb, int n) {
    if (threadIdx.x == 0) {
        int run = 0;
        for (int b = 0; b < nb; b++) {
            int v = g_bsum[b];
            g_bsum[b] = run;
            run += v;
        }
        g_rowptr[n] = run;
    }
}

__global__ __launch_bounds__(SCAN_BS) void k_scanC(int n) {
    __shared__ int s[SCAN_BS];
    int t = threadIdx.x;
    int i = blockIdx.x * SCAN_BS + t;
    int c = (i < n) ? g_cnt[i] : 0;
    s[t] = c;
    __syncthreads();
    for (int off = 1; off < SCAN_BS; off <<= 1) {
        int v = (t >= off) ? s[t - off] : 0;
        __syncthreads();
        s[t] += v;
        __syncthreads();
    }
    if (i < n) {
        int ex = s[t] - c + g_bsum[blockIdx.x];
        g_rowptr[i] = ex;
        g_cursor[i] = ex;
        g_dinv[i]   = rsqrtf((float)(c + 1));
    }
}

__global__ void k_fill(const int* __restrict__ src, const int* __restrict__ dst, int e) {
    int i = blockIdx.x * blockDim.x + threadIdx.x;
    int n4 = e >> 2;
    if (i < n4) {
        int4 s = __ldg(reinterpret_cast<const int4*>(src) + i);
        int4 d = __ldg(reinterpret_cast<const int4*>(dst) + i);
        g_col[atomicAdd(&g_cursor[d.x], 1)] = s.x;
        g_col[atomicAdd(&g_cursor[d.y], 1)] = s.y;
        g_col[atomicAdd(&g_cursor[d.z], 1)] = s.z;
        g_col[atomicAdd(&g_cursor[d.w], 1)] = s.w;
    } else {
        int j = n4 * 4 + (i - n4);
        if (j < e) g_col[atomicAdd(&g_cursor[dst[j]], 1)] = src[j];
    }
}

// ---------------------------------------------------------------------------
// 3xTF32 mma.sync GEMM: Y[row] = (relu?)X[row] @ W
// Block: 64 rows x 128 cols, K=128 full. 256 threads (8 warps, 2x4 warp grid).
// D = Ah*Bh + Ah*Bl + Al*Bh (fp32-class accuracy).
// smem: Ah/Al [64][132] u32, Bh/Bl [128][136] u32  (padded, conflict-free).
// ---------------------------------------------------------------------------
#define LDA 132
#define LDB 136
#define SM_A (64 * LDA)
#define SM_B (128 * LDB)
#define SM_GEMM_BYTES ((2 * SM_A + 2 * SM_B) * 4)

__device__ __forceinline__ void mma_tf32(float* c, const uint32_t* a, const uint32_t* b) {
    asm volatile(
        "mma.sync.aligned.m16n8k8.row.col.f32.tf32.tf32.f32 "
        "{%0,%1,%2,%3}, {%4,%5,%6,%7}, {%8,%9}, {%0,%1,%2,%3};"
        : "+f"(c[0]), "+f"(c[1]), "+f"(c[2]), "+f"(c[3])
        : "r"(a[0]), "r"(a[1]), "r"(a[2]), "r"(a[3]), "r"(b[0]), "r"(b[1]));
}

template <bool RELU>
__global__ __launch_bounds__(256) void k_gemm_mma(const float* __restrict__ X,
                                                  const float* __restrict__ W,
                                                  float* __restrict__ Y, int n) {
    extern __shared__ uint32_t sm[];
    uint32_t* sAh = sm;
    uint32_t* sAl = sAh + SM_A;
    uint32_t* sBh = sAl + SM_A;
    uint32_t* sBl = sBh + SM_B;

    const int tid  = threadIdx.x;
    const int row0 = blockIdx.x * 64;

    // ---- A tile load + split ----
#pragma unroll
    for (int idx = tid; idx < 64 * 32; idx += 256) {
        int r  = idx >> 5;
        int c4 = idx & 31;
        int row = row0 + r;
        float4 v = make_float4(0.f, 0.f, 0.f, 0.f);
        if (row < n) v = __ldg(reinterpret_cast<const float4*>(X + (size_t)row * DD) + c4);
        if (RELU) {
            v.x = fmaxf(v.x, 0.f); v.y = fmaxf(v.y, 0.f);
            v.z = fmaxf(v.z, 0.f); v.w = fmaxf(v.w, 0.f);
        }
        uint4 h, l;
        h.x = f2tf(v.x); l.x = f2tf(v.x - __uint_as_float(h.x));
        h.y = f2tf(v.y); l.y = f2tf(v.y - __uint_as_float(h.y));
        h.z = f2tf(v.z); l.z = f2tf(v.z - __uint_as_float(h.z));
        h.w = f2tf(v.w); l.w = f2tf(v.w - __uint_as_float(h.w));
        *reinterpret_cast<uint4*>(&sAh[r * LDA + c4 * 4]) = h;
        *reinterpret_cast<uint4*>(&sAl[r * LDA + c4 * 4]) = l;
    }

    // ---- B tile load + split: sB[k][n] = W[k][n] ----
#pragma unroll
    for (int idx = tid; idx < 128 * 32; idx += 256) {
        int k  = idx >> 5;
        int c4 = idx & 31;
        float4 v = __ldg(reinterpret_cast<const float4*>(W + (size_t)k * DD) + c4);
        uint4 h, l;
        h.x = f2tf(v.x); l.x = f2tf(v.x - __uint_as_float(h.x));
        h.y = f2tf(v.y); l.y = f2tf(v.y - __uint_as_float(h.y));
        h.z = f2tf(v.z); l.z = f2tf(v.z - __uint_as_float(h.z));
        h.w = f2tf(v.w); l.w = f2tf(v.w - __uint_as_float(h.w));
        *reinterpret_cast<uint4*>(&sBh[k * LDB + c4 * 4]) = h;
        *reinterpret_cast<uint4*>(&sBl[k * LDB + c4 * 4]) = l;
    }
    __syncthreads();

    const int wid  = tid >> 5;
    const int lane = tid & 31;
    const int gid  = lane >> 2;   // group id (0..7)
    const int tig  = lane & 3;    // thread in group (0..3)
    const int wm   = wid & 1;     // 2 warps along M (32 rows each)
    const int wn   = wid >> 1;    // 4 warps along N (32 cols each)

    float acc[2][4][4];
#pragma unroll
    for (int mi = 0; mi < 2; mi++)
#pragma unroll
        for (int ni = 0; ni < 4; ni++)
#pragma unroll
            for (int j = 0; j < 4; j++) acc[mi][ni][j] = 0.f;

    for (int p = 0; p < 3; p++) {
        const uint32_t* As = (p == 2) ? sAl : sAh;
        const uint32_t* Bs = (p == 1) ? sBl : sBh;
#pragma unroll
        for (int ks = 0; ks < 16; ks++) {
            const int k0 = ks * 8;
            uint32_t a[2][4];
#pragma unroll
            for (int mi = 0; mi < 2; mi++) {
                int rb = wm * 32 + mi * 16;
                a[mi][0] = As[(rb + gid) * LDA + k0 + tig];
                a[mi][1] = As[(rb + gid + 8) * LDA + k0 + tig];
                a[mi][2] = As[(rb + gid) * LDA + k0 + tig + 4];
                a[mi][3] = As[(rb + gid + 8) * LDA + k0 + tig + 4];
            }
            uint32_t b[4][2];
#pragma unroll
            for (int ni = 0; ni < 4; ni++) {
                int nb = wn * 32 + ni * 8;
                b[ni][0] = Bs[(k0 + tig) * LDB + nb + gid];
                b[ni][1] = Bs[(k0 + tig + 4) * LDB + nb + gid];
            }
#pragma unroll
            for (int mi = 0; mi < 2; mi++)
#pragma unroll
                for (int ni = 0; ni < 4; ni++)
                    mma_tf32(acc[mi][ni], a[mi], b[ni]);
        }
    }

    // ---- Epilogue ----
#pragma unroll
    for (int mi = 0; mi < 2; mi++) {
        int r0 = row0 + wm * 32 + mi * 16 + gid;
#pragma unroll
        for (int ni = 0; ni < 4; ni++) {
            int col = wn * 32 + ni * 8 + tig * 2;
            if (r0 < n)
                *reinterpret_cast<float2*>(Y + (size_t)r0 * DD + col) =
                    make_float2(acc[mi][ni][0], acc[mi][ni][1]);
            if (r0 + 8 < n)
                *reinterpret_cast<float2*>(Y + (size_t)(r0 + 8) * DD + col) =
                    make_float2(acc[mi][ni][2], acc[mi][ni][3]);
        }
    }
}

// ---------------------------------------------------------------------------
// Gather: out[i] = dinv[i] * (dinv[i]*h[i] + sum_in dinv[s]*h[s]) + b
// One warp per node; lane owns one float4 chunk.
// ---------------------------------------------------------------------------
__global__ __launch_bounds__(256) void k_gather(const float* __restrict__ hs,
                                                const float* __restrict__ b,
                                                float* __restrict__ out, int n) {
    int g    = blockIdx.x * blockDim.x + threadIdx.x;
    int node = g >> 5;
    int lane = g & 31;
    if (node >= n) return;

    const float4* H = reinterpret_cast<const float4*>(hs);
    int beg = g_rowptr[node];
    int end = g_rowptr[node + 1];

    float dn = g_dinv[node];
    float4 sv = __ldg(&H[node * 32 + lane]);
    float4 acc = make_float4(sv.x * dn, sv.y * dn, sv.z * dn, sv.w * dn);

    int e = beg;
    for (; e + 4 <= end; e += 4) {
        int s0 = g_col[e + 0], s1 = g_col[e + 1];
        int s2 = g_col[e + 2], s3 = g_col[e + 3];
        float d0 = g_dinv[s0], d1 = g_dinv[s1], d2 = g_dinv[s2], d3 = g_dinv[s3];
        float4 v0 = __ldg(&H[s0 * 32 + lane]);
        float4 v1 = __ldg(&H[s1 * 32 + lane]);
        float4 v2 = __ldg(&H[s2 * 32 + lane]);
        float4 v3 = __ldg(&H[s3 * 32 + lane]);
        acc.x += v0.x * d0 + v1.x * d1 + v2.x * d2 + v3.x * d3;
        acc.y += v0.y * d0 + v1.y * d1 + v2.y * d2 + v3.y * d3;
        acc.z += v0.z * d0 + v1.z * d1 + v2.z * d2 + v3.z * d3;
        acc.w += v0.w * d0 + v1.w * d1 + v2.w * d2 + v3.w * d3;
    }
    for (; e < end; e++) {
        int s = g_col[e];
        float ds = g_dinv[s];
        float4 v = __ldg(&H[s * 32 + lane]);
        acc.x += v.x * ds; acc.y += v.y * ds; acc.z += v.z * ds; acc.w += v.w * ds;
    }

    float4 bb = __ldg(reinterpret_cast<const float4*>(b) + lane);
    float4 o;
    o.x = fmaf(acc.x, dn, bb.x);
    o.y = fmaf(acc.y, dn, bb.y);
    o.z = fmaf(acc.z, dn, bb.z);
    o.w = fmaf(acc.w, dn, bb.w);
    reinterpret_cast<float4*>(out)[node * 32 + lane] = o;
}

// ---------------------------------------------------------------------------
// Stream/event resources
// ---------------------------------------------------------------------------
static cudaStream_t g_s1 = nullptr;
static cudaEvent_t  g_evf = nullptr, g_evj = nullptr;
namespace {
struct StreamInit {
    StreamInit() {
        if (cudaStreamCreateWithFlags(&g_s1, cudaStreamNonBlocking) != cudaSuccess) g_s1 = nullptr;
        if (cudaEventCreateWithFlags(&g_evf, cudaEventDisableTiming) != cudaSuccess) g_evf = nullptr;
        if (cudaEventCreateWithFlags(&g_evj, cudaEventDisableTiming) != cudaSuccess) g_evj = nullptr;
        cudaGetLastError();
    }
} g_stream_init;
}

// ---------------------------------------------------------------------------
// Launch
// ---------------------------------------------------------------------------
extern "C" void kernel_launch(void* const* d_in, const int* in_sizes, int n_in,
                              void* d_out, int out_size) {
    const float* x  = (const float*)d_in[0];
    const int*   ei = (const int*)d_in[1];
    const float* W1 = (const float*)d_in[2];
    const float* b1 = (const float*)d_in[3];
    const float* W2 = (const float*)d_in[4];
    const float* b2 = (const float*)d_in[5];
    float* out = (float*)d_out;

    const int n = in_sizes[0] / DD;   // 50000
    const int e = in_sizes[1] / 2;    // 800000
    const int* src = ei;
    const int* dst = ei + e;

    float *p_h = nullptr, *p_a = nullptr;
    cudaGetSymbolAddress((void**)&p_h, g_h);
    cudaGetSymbolAddress((void**)&p_a, g_a);

    cudaFuncSetAttribute(k_gemm_mma<false>, cudaFuncAttributeMaxDynamicSharedMemorySize, SM_GEMM_BYTES);
    cudaFuncSetAttribute(k_gemm_mma<true>,  cudaFuncAttributeMaxDynamicSharedMemorySize, SM_GEMM_BYTES);

    const int T = 256;
    const int nb = (n + SCAN_BS - 1) / SCAN_BS;
    const int e4threads = (e >> 2) + 4;
    const int gemm_blocks = (n + 63) / 64;
    const long long nwt = (long long)n * 32;
    const int gath_blocks = (int)((nwt + T - 1) / T);

    const bool fork = (g_s1 && g_evf && g_evj);
    cudaStream_t sc = fork ? g_s1 : (cudaStream_t)0;

    if (fork) {
        cudaEventRecord(g_evf, 0);
        cudaStreamWaitEvent(g_s1, g_evf, 0);
    }

    // CSR + normalization (side stream, overlapped with GEMM-1)
    k_zero <<<(n + T - 1) / T, T, 0, sc>>>(n);
    k_hist <<<(e4threads + T - 1) / T, T, 0, sc>>>(dst, e);
    k_scanA<<<nb, SCAN_BS, 0, sc>>>(n);
    k_scanB<<<1, 32, 0, sc>>>(nb, n);
    k_scanC<<<nb, SCAN_BS, 0, sc>>>(n);
    k_fill <<<(e4threads + T - 1) / T, T, 0, sc>>>(src, dst, e);

    // GEMM-1 on main stream (independent of CSR)
    k_gemm_mma<false><<<gemm_blocks, 256, SM_GEMM_BYTES>>>(x, W1, p_h, n);

    if (fork) {
        cudaEventRecord(g_evj, g_s1);
        cudaStreamWaitEvent(0, g_evj, 0);
    }

    // Layer 1 aggregate, Layer 2
    k_gather<<<gath_blocks, T>>>(p_h, b1, p_a, n);
    k_gemm_mma<true><<<gemm_blocks, 256, SM_GEMM_BYTES>>>(p_a, W2, p_h, n);
    k_gather<<<gath_blocks, T>>>(p_h, b2, out, n);
}